// round 8
// baseline (speedup 1.0000x reference)
#include <cuda_runtime.h>
#include <stdint.h>

#define BATCH 8192
#define IN_F  16384
#define HID   384
#define NOUT  10
#define KW    (IN_F / 32)      // 512 k-words total
#define KWC   8                // k-words per chunk
#define NCH   (KW / KWC)       // 64 chunks
#define CTA_M 8
#define NTHR  64

#define B_CH_W  (KWC * HID)    // 3072 words = 12288 B
#define A_CH_W  (KWC * CTA_M)  // 64 words = 256 B
#define B_BYTES (B_CH_W * 4)
#define A_BYTES (A_CH_W * 4)
#define SMEMSZ  (2 * (B_BYTES + A_BYTES))   // 25088 B

// ---------------- scratch globals ------------------------------------------
__device__ uint32_t  g_wbt[(size_t)KW * HID];   // W1 sign bits, [kword][hid]
__device__ short     g_h[(size_t)BATCH * HID];
__device__ long long g_sum[HID];
__device__ long long g_sumsq[HID];
__device__ float     g_A[HID];
__device__ float     g_B[HID];

// ---------------- PTX helpers ----------------------------------------------
__device__ __forceinline__ uint32_t smem_u32(const void* p) {
    uint32_t a;
    asm("{ .reg .u64 t; cvta.to.shared.u64 t, %1; cvt.u32.u64 %0, t; }"
        : "=r"(a) : "l"(p));
    return a;
}
#define CP16(s, g) \
    asm volatile("{ .reg .u64 gp; cvta.to.global.u64 gp, %1; " \
                 "cp.async.cg.shared.global [%0], [gp], 16; }" \
                 :: "r"(s), "l"(g) : "memory")
#define CPCOMMIT() asm volatile("cp.async.commit_group;" ::: "memory")
#define CPWAIT0()  asm volatile("cp.async.wait_group 0;" ::: "memory")
#define LDS4(r, a) \
    asm volatile("ld.shared.v4.b32 {%0,%1,%2,%3}, [%4];" \
                 : "=r"((r)[0]), "=r"((r)[1]), "=r"((r)[2]), "=r"((r)[3]) : "r"(a))

// ---------------- zero BN accumulators -------------------------------------
__global__ void zero_sums_kernel() {
    int j = threadIdx.x;
    if (j < HID) { g_sum[j] = 0; g_sumsq[j] = 0; }
}

// ---------------- W1 -> sign bits, transposed [kword][hid] ------------------
// kword (q*4+j), bit l  <->  W1[r, q*128 + 4*l + j]   (same perm used for x)
__global__ __launch_bounds__(256) void packw_kernel(const float* __restrict__ W1) {
    int gw   = (blockIdx.x * 256 + threadIdx.x) >> 5;
    int lane = threadIdx.x & 31;
    int r = gw >> 7;          // 0..383
    int q = gw & 127;         // 0..127
    float4 f = *reinterpret_cast<const float4*>(W1 + (size_t)r * IN_F + q * 128 + lane * 4);
    unsigned b0 = __ballot_sync(0xffffffffu, f.x < 0.f);
    unsigned b1 = __ballot_sync(0xffffffffu, f.y < 0.f);
    unsigned b2 = __ballot_sync(0xffffffffu, f.z < 0.f);
    unsigned b3 = __ballot_sync(0xffffffffu, f.w < 0.f);
    if (lane == 0) {
        g_wbt[(size_t)(q * 4 + 0) * HID + r] = b0;
        g_wbt[(size_t)(q * 4 + 1) * HID + r] = b1;
        g_wbt[(size_t)(q * 4 + 2) * HID + r] = b2;
        g_wbt[(size_t)(q * 4 + 3) * HID + r] = b3;
    }
}

// ---------------- CSA popcount GEMM, fused sign(x), 7 CTAs/SM ---------------
// 1024 CTAs: M=8 rows, N=384, full K. Warp w (of 2): rows 4w..4w+3.
// Lane n: cols 12n..12n+11. Depth-1 CSA: 0.5 POPC + 2 LOP3 per word-cell.
__global__ __launch_bounds__(NTHR, 7) void gemm_pop_kernel(const float* __restrict__ x) {
    extern __shared__ uint32_t smem[];
    const uint32_t sb  = smem_u32(smem);
    const int tid  = threadIdx.x;
    const int wid  = tid >> 5;
    const int lane = tid & 31;
    const int m0   = blockIdx.x * CTA_M;

    uint32_t ones[4][12];
    int      acc [4][12];
#pragma unroll
    for (int i = 0; i < 4; i++)
#pragma unroll
        for (int j = 0; j < 12; j++) { ones[i][j] = 0u; acc[i][j] = 0; }

    // B chunk: 12KB cp.async copy (12 x 16B per thread)
    auto loadB = [&](int c, int buf) {
        const char* src = (const char*)g_wbt + (size_t)c * B_BYTES;
        uint32_t dst = sb + buf * B_BYTES;
#pragma unroll
        for (int i = 0; i < 12; i++) {
            int u = tid + NTHR * i;
            CP16(dst + u * 16, src + (size_t)u * 16);
        }
    };
    // A chunk: read x fp32, ballot-binarize, store [kw][row] bit-words.
    // 16 tasks (8 rows x 2 col-groups of 128 floats), 8 per warp.
    auto convA = [&](int c, int buf) {
        uint32_t* As = smem + 2 * B_CH_W + buf * A_CH_W;
#pragma unroll 4
        for (int t = 0; t < 8; t++) {
            int G = wid * 8 + t;
            int row = G >> 1, gcol = G & 1;
            float4 f = *reinterpret_cast<const float4*>(
                x + (size_t)(m0 + row) * IN_F + c * (KWC * 32) + gcol * 128 + lane * 4);
            unsigned b0 = __ballot_sync(0xffffffffu, f.x < 0.f);
            unsigned b1 = __ballot_sync(0xffffffffu, f.y < 0.f);
            unsigned b2 = __ballot_sync(0xffffffffu, f.z < 0.f);
            unsigned b3 = __ballot_sync(0xffffffffu, f.w < 0.f);
            if (lane == 0) {
                As[(gcol * 4 + 0) * CTA_M + row] = b0;
                As[(gcol * 4 + 1) * CTA_M + row] = b1;
                As[(gcol * 4 + 2) * CTA_M + row] = b2;
                As[(gcol * 4 + 3) * CTA_M + row] = b3;
            }
        }
    };

    loadB(0, 0); CPCOMMIT();
    convA(0, 0);
    CPWAIT0(); __syncthreads();

    for (int c = 0; c < NCH; c++) {
        const int buf = c & 1;
        if (c + 1 < NCH) { loadB(c + 1, buf ^ 1); CPCOMMIT(); convA(c + 1, buf ^ 1); }

        const uint32_t bB = sb + buf * B_BYTES;
        const uint32_t bA = sb + 2 * B_BYTES + buf * A_BYTES;
#pragma unroll
        for (int kp = 0; kp < KWC / 2; kp++) {
            uint32_t a0[4], a1[4];
            LDS4(a0, bA + (2 * kp)     * (CTA_M * 4) + wid * 16);   // broadcast
            LDS4(a1, bA + (2 * kp + 1) * (CTA_M * 4) + wid * 16);
#pragma unroll
            for (int g = 0; g < 3; g++) {     // col groups of 4 (small live set)
                uint32_t b0[4], b1[4];
                LDS4(b0, bB + (2 * kp)     * (HID * 4) + lane * 48 + g * 16);
                LDS4(b1, bB + (2 * kp + 1) * (HID * 4) + lane * 48 + g * 16);
#pragma unroll
                for (int i = 0; i < 4; i++)
#pragma unroll
                    for (int jj = 0; jj < 4; jj++) {
                        const int j = g * 4 + jj;
                        uint32_t u = a0[i] ^ b0[jj];
                        uint32_t v = a1[i] ^ b1[jj];
                        uint32_t o = ones[i][j];
                        uint32_t cy = (o & u) | (o & v) | (u & v);  // LOP3 0xE8
                        ones[i][j] = o ^ u ^ v;                     // LOP3 0x96
                        acc[i][j] += __popc(cy);
                    }
            }
        }
        if (c + 1 < NCH) CPWAIT0();
        __syncthreads();
    }

    // mismatch = 2*acc + popc(ones);  h = IN_F - 2*mismatch
#pragma unroll
    for (int i = 0; i < 4; i++) {
        const int row = m0 + wid * 4 + i;
        short2* dst = reinterpret_cast<short2*>(g_h + (size_t)row * HID + lane * 12);
#pragma unroll
        for (int jp = 0; jp < 6; jp++) {
            int t0 = 2 * acc[i][2 * jp]     + __popc(ones[i][2 * jp]);
            int t1 = 2 * acc[i][2 * jp + 1] + __popc(ones[i][2 * jp + 1]);
            dst[jp] = make_short2((short)(IN_F - 2 * t0), (short)(IN_F - 2 * t1));
        }
    }
}

// ---------------- BN batch statistics (exact integer sums) -----------------
__global__ void stats_kernel() {
    const int cg = blockIdx.x, rc = blockIdx.y;
    const int c = threadIdx.x & 31, t = threadIdx.x >> 5;
    const int col = cg * 32 + c;
    int s = 0;
    long long s2 = 0;
    const int rbase = rc * 1024;
    for (int r = rbase + t; r < rbase + 1024; r += 8) {
        int v = g_h[(size_t)r * HID + col];
        s += v;
        s2 += (long long)v * v;
    }
    __shared__ int       ss [8][32];
    __shared__ long long ss2[8][32];
    ss[t][c] = s; ss2[t][c] = s2;
    __syncthreads();
    if (t == 0) {
        long long S = 0, S2 = 0;
#pragma unroll
        for (int u = 0; u < 8; u++) { S += ss[u][c]; S2 += ss2[u][c]; }
        atomicAdd((unsigned long long*)&g_sum[col],   (unsigned long long)S);
        atomicAdd((unsigned long long*)&g_sumsq[col], (unsigned long long)S2);
    }
}

// ---------------- fold BN into affine --------------------------------------
__global__ void finalize_kernel(const float* __restrict__ gamma,
                                const float* __restrict__ beta) {
    int j = threadIdx.x;
    if (j >= HID) return;
    double mean = (double)g_sum[j]   / (double)BATCH;
    double var  = (double)g_sumsq[j] / (double)BATCH - mean * mean;
    float a = gamma[j] * (float)(1.0 / sqrt(var + 1e-5));
    g_A[j] = a;
    g_B[j] = beta[j] - (float)mean * a;
}

// ---------------- output layer ---------------------------------------------
__global__ __launch_bounds__(256) void out_kernel(const float* __restrict__ W4,
                                                  float* __restrict__ out) {
    int gt = blockIdx.x * blockDim.x + threadIdx.x;
    int row = gt >> 5, lane = gt & 31;
    if (row >= BATCH) return;
    float acc[NOUT];
#pragma unroll
    for (int o = 0; o < NOUT; o++) acc[o] = 0.f;
    for (int j = lane; j < HID; j += 32) {
        int hv = g_h[(size_t)row * HID + j];
        float v = (float)hv * g_A[j] + g_B[j];
        float s = (v > 0.f) ? 1.f : ((v < 0.f) ? -1.f : 0.f);
#pragma unroll
        for (int o = 0; o < NOUT; o++) {
            float w = __ldg(&W4[o * HID + j]);
            float ws = (w > 0.f) ? 1.f : ((w < 0.f) ? -1.f : 0.f);
            acc[o] = fmaf(s, ws, acc[o]);
        }
    }
#pragma unroll
    for (int o = 0; o < NOUT; o++)
#pragma unroll
        for (int off = 16; off; off >>= 1)
            acc[o] += __shfl_down_sync(0xffffffffu, acc[o], off);
    if (lane == 0) {
#pragma unroll
        for (int o = 0; o < NOUT; o++) out[(size_t)row * NOUT + o] = acc[o];
    }
}

// ---------------- launch ----------------------------------------------------
extern "C" void kernel_launch(void* const* d_in, const int* in_sizes, int n_in,
                              void* d_out, int out_size) {
    const float* x     = (const float*)d_in[0];
    const float* W1    = (const float*)d_in[1];
    const float* gamma = (const float*)d_in[2];
    const float* beta  = (const float*)d_in[3];
    const float* W4    = (const float*)d_in[4];
    float* out = (float*)d_out;

    zero_sums_kernel<<<1, HID>>>();
    packw_kernel<<<(HID * 128) / 8, 256>>>(W1);   // 6144 blocks

    cudaFuncSetAttribute(gemm_pop_kernel,
                         cudaFuncAttributeMaxDynamicSharedMemorySize, SMEMSZ);
    gemm_pop_kernel<<<BATCH / CTA_M, NTHR, SMEMSZ>>>(x);   // 1024 CTAs, 1 wave

    stats_kernel<<<dim3(HID / 32, BATCH / 1024), 256>>>();
    finalize_kernel<<<1, HID>>>(gamma, beta);
    out_kernel<<<(BATCH * 32) / 256, 256>>>(W4, out);
}

// round 10
// speedup vs baseline: 1.0189x; 1.0189x over previous
#include <cuda_runtime.h>
#include <stdint.h>

#define BATCH 8192
#define IN_F  16384
#define HID   384
#define NOUT  10
#define KW    (IN_F / 32)      // 512 k-words total
#define KWC   16               // k-words per chunk
#define NCH   (KW / KWC)       // 32 chunks
#define CTA_M 16
#define NTHR  128

#define B_CH_W  (KWC * HID)    // 6144 words = 24576 B
#define A_CH_W  (KWC * CTA_M)  // 256 words = 1024 B
#define B_BYTES (B_CH_W * 4)
#define A_BYTES (A_CH_W * 4)
#define SMEMSZ  (2 * (B_BYTES + A_BYTES))   // 51200 B

// ---------------- scratch globals ------------------------------------------
__device__ uint32_t  g_wbt[(size_t)KW * HID];   // W1 sign bits, [kword][hid]
__device__ short     g_h[(size_t)BATCH * HID];
__device__ long long g_sum[HID];
__device__ long long g_sumsq[HID];
__device__ float     g_A[HID];
__device__ float     g_B[HID];

// ---------------- PTX helpers ----------------------------------------------
__device__ __forceinline__ uint32_t smem_u32(const void* p) {
    uint32_t a;
    asm("{ .reg .u64 t; cvta.to.shared.u64 t, %1; cvt.u32.u64 %0, t; }"
        : "=r"(a) : "l"(p));
    return a;
}
#define CP16(s, g) \
    asm volatile("{ .reg .u64 gp; cvta.to.global.u64 gp, %1; " \
                 "cp.async.cg.shared.global [%0], [gp], 16; }" \
                 :: "r"(s), "l"(g) : "memory")
#define CPCOMMIT() asm volatile("cp.async.commit_group;" ::: "memory")
#define CPWAIT0()  asm volatile("cp.async.wait_group 0;" ::: "memory")
#define LDS4(r, a) \
    asm volatile("ld.shared.v4.b32 {%0,%1,%2,%3}, [%4];" \
                 : "=r"((r)[0]), "=r"((r)[1]), "=r"((r)[2]), "=r"((r)[3]) : "r"(a))

// ---------------- zero BN accumulators -------------------------------------
__global__ void zero_sums_kernel() {
    int j = threadIdx.x;
    if (j < HID) { g_sum[j] = 0; g_sumsq[j] = 0; }
}

// ---------------- W1 -> sign bits, transposed [kword][hid] ------------------
// kword (q*4+j), bit l  <->  W1[r, q*128 + 4*l + j]   (same perm used for x)
__global__ __launch_bounds__(256) void packw_kernel(const float* __restrict__ W1) {
    int gw   = (blockIdx.x * 256 + threadIdx.x) >> 5;
    int lane = threadIdx.x & 31;
    int r = gw >> 7;          // 0..383
    int q = gw & 127;         // 0..127
    float4 f = *reinterpret_cast<const float4*>(W1 + (size_t)r * IN_F + q * 128 + lane * 4);
    unsigned b0 = __ballot_sync(0xffffffffu, f.x < 0.f);
    unsigned b1 = __ballot_sync(0xffffffffu, f.y < 0.f);
    unsigned b2 = __ballot_sync(0xffffffffu, f.z < 0.f);
    unsigned b3 = __ballot_sync(0xffffffffu, f.w < 0.f);
    if (lane == 0) {
        g_wbt[(size_t)(q * 4 + 0) * HID + r] = b0;
        g_wbt[(size_t)(q * 4 + 1) * HID + r] = b1;
        g_wbt[(size_t)(q * 4 + 2) * HID + r] = b2;
        g_wbt[(size_t)(q * 4 + 3) * HID + r] = b3;
    }
}

// ---------------- CSA popcount GEMM, fused sign(x), single wave -------------
// 512 CTAs (M=16, N=384, full K), 128 thr, 4 CTAs/SM. Warp w: rows 4w..4w+3.
// Lane n: cols 12n..12n+11. Depth-1 CSA: 0.5 POPC + 2 alu-LOP3 per word-cell.
__global__ __launch_bounds__(NTHR, 4) void gemm_pop_kernel(const float* __restrict__ x) {
    extern __shared__ uint32_t smem[];
    const uint32_t sb  = smem_u32(smem);
    const int tid  = threadIdx.x;
    const int wid  = tid >> 5;
    const int lane = tid & 31;
    const int m0   = blockIdx.x * CTA_M;

    uint32_t ones[4][12];
    int      acc [4][12];
#pragma unroll
    for (int i = 0; i < 4; i++)
#pragma unroll
        for (int j = 0; j < 12; j++) { ones[i][j] = 0u; acc[i][j] = 0; }

    // B chunk: 24KB cp.async copy (12 x 16B per thread)
    auto loadB = [&](int c, int buf) {
        const char* src = (const char*)g_wbt + (size_t)c * B_BYTES;
        uint32_t dst = sb + buf * B_BYTES;
#pragma unroll
        for (int i = 0; i < 12; i++) {
            int u = tid + NTHR * i;
            CP16(dst + u * 16, src + (size_t)u * 16);
        }
    };
    // A chunk: read x fp32, ballot-binarize, store [kw][row] bit-words.
    // 64 tasks (16 rows x 4 col-groups of 128 floats), 16 per warp.
    auto convA = [&](int c, int buf) {
        uint32_t* As = smem + 2 * B_CH_W + buf * A_CH_W;
#pragma unroll 4
        for (int t = 0; t < 16; t++) {
            int G = wid * 16 + t;
            int row = G >> 2, gcol = G & 3;
            float4 f = *reinterpret_cast<const float4*>(
                x + (size_t)(m0 + row) * IN_F + c * (KWC * 32) + gcol * 128 + lane * 4);
            unsigned b0 = __ballot_sync(0xffffffffu, f.x < 0.f);
            unsigned b1 = __ballot_sync(0xffffffffu, f.y < 0.f);
            unsigned b2 = __ballot_sync(0xffffffffu, f.z < 0.f);
            unsigned b3 = __ballot_sync(0xffffffffu, f.w < 0.f);
            if (lane == 0) {
                As[(gcol * 4 + 0) * CTA_M + row] = b0;
                As[(gcol * 4 + 1) * CTA_M + row] = b1;
                As[(gcol * 4 + 2) * CTA_M + row] = b2;
                As[(gcol * 4 + 3) * CTA_M + row] = b3;
            }
        }
    };

    loadB(0, 0); CPCOMMIT();
    convA(0, 0);
    CPWAIT0(); __syncthreads();

    for (int c = 0; c < NCH; c++) {
        const int buf = c & 1;
        if (c + 1 < NCH) { loadB(c + 1, buf ^ 1); CPCOMMIT(); convA(c + 1, buf ^ 1); }

        const uint32_t bB = sb + buf * B_BYTES;
        const uint32_t bA = sb + 2 * B_BYTES + buf * A_BYTES;
#pragma unroll
        for (int kp = 0; kp < KWC / 2; kp++) {
            uint32_t a0[4], a1[4];
            LDS4(a0, bA + (2 * kp)     * (CTA_M * 4) + wid * 16);   // broadcast
            LDS4(a1, bA + (2 * kp + 1) * (CTA_M * 4) + wid * 16);
#pragma unroll
            for (int g = 0; g < 3; g++) {     // col groups of 4 (small live set)
                uint32_t b0[4], b1[4];
                LDS4(b0, bB + (2 * kp)     * (HID * 4) + lane * 48 + g * 16);
                LDS4(b1, bB + (2 * kp + 1) * (HID * 4) + lane * 48 + g * 16);
#pragma unroll
                for (int i = 0; i < 4; i++)
#pragma unroll
                    for (int jj = 0; jj < 4; jj++) {
                        const int j = g * 4 + jj;
                        uint32_t u = a0[i] ^ b0[jj];
                        uint32_t v = a1[i] ^ b1[jj];
                        uint32_t o = ones[i][j];
                        uint32_t cy = (o & u) | (o & v) | (u & v);  // LOP3 0xE8
                        ones[i][j] = o ^ u ^ v;                     // LOP3 0x96
                        acc[i][j] += __popc(cy);
                    }
            }
        }
        if (c + 1 < NCH) CPWAIT0();
        __syncthreads();
    }

    // mismatch = 2*acc + popc(ones);  h = IN_F - 2*mismatch
#pragma unroll
    for (int i = 0; i < 4; i++) {
        const int row = m0 + wid * 4 + i;
        short2* dst = reinterpret_cast<short2*>(g_h + (size_t)row * HID + lane * 12);
#pragma unroll
        for (int jp = 0; jp < 6; jp++) {
            int t0 = 2 * acc[i][2 * jp]     + __popc(ones[i][2 * jp]);
            int t1 = 2 * acc[i][2 * jp + 1] + __popc(ones[i][2 * jp + 1]);
            dst[jp] = make_short2((short)(IN_F - 2 * t0), (short)(IN_F - 2 * t1));
        }
    }
}

// ---------------- BN batch statistics (exact integer sums) -----------------
__global__ void stats_kernel() {
    const int cg = blockIdx.x, rc = blockIdx.y;
    const int c = threadIdx.x & 31, t = threadIdx.x >> 5;
    const int col = cg * 32 + c;
    int s = 0;
    long long s2 = 0;
    const int rbase = rc * 1024;
    for (int r = rbase + t; r < rbase + 1024; r += 8) {
        int v = g_h[(size_t)r * HID + col];
        s += v;
        s2 += (long long)v * v;
    }
    __shared__ int       ss [8][32];
    __shared__ long long ss2[8][32];
    ss[t][c] = s; ss2[t][c] = s2;
    __syncthreads();
    if (t == 0) {
        long long S = 0, S2 = 0;
#pragma unroll
        for (int u = 0; u < 8; u++) { S += ss[u][c]; S2 += ss2[u][c]; }
        atomicAdd((unsigned long long*)&g_sum[col],   (unsigned long long)S);
        atomicAdd((unsigned long long*)&g_sumsq[col], (unsigned long long)S2);
    }
}

// ---------------- fold BN into affine --------------------------------------
__global__ void finalize_kernel(const float* __restrict__ gamma,
                                const float* __restrict__ beta) {
    int j = threadIdx.x;
    if (j >= HID) return;
    double mean = (double)g_sum[j]   / (double)BATCH;
    double var  = (double)g_sumsq[j] / (double)BATCH - mean * mean;
    float a = gamma[j] * (float)(1.0 / sqrt(var + 1e-5));
    g_A[j] = a;
    g_B[j] = beta[j] - (float)mean * a;
}

// ---------------- output layer ---------------------------------------------
__global__ __launch_bounds__(256) void out_kernel(const float* __restrict__ W4,
                                                  float* __restrict__ out) {
    int gt = blockIdx.x * blockDim.x + threadIdx.x;
    int row = gt >> 5, lane = gt & 31;
    if (row >= BATCH) return;
    float acc[NOUT];
#pragma unroll
    for (int o = 0; o < NOUT; o++) acc[o] = 0.f;
    for (int j = lane; j < HID; j += 32) {
        int hv = g_h[(size_t)row * HID + j];
        float v = (float)hv * g_A[j] + g_B[j];
        float s = (v > 0.f) ? 1.f : ((v < 0.f) ? -1.f : 0.f);
#pragma unroll
        for (int o = 0; o < NOUT; o++) {
            float w = __ldg(&W4[o * HID + j]);
            float ws = (w > 0.f) ? 1.f : ((w < 0.f) ? -1.f : 0.f);
            acc[o] = fmaf(s, ws, acc[o]);
        }
    }
#pragma unroll
    for (int o = 0; o < NOUT; o++)
#pragma unroll
        for (int off = 16; off; off >>= 1)
            acc[o] += __shfl_down_sync(0xffffffffu, acc[o], off);
    if (lane == 0) {
#pragma unroll
        for (int o = 0; o < NOUT; o++) out[(size_t)row * NOUT + o] = acc[o];
    }
}

// ---------------- launch ----------------------------------------------------
extern "C" void kernel_launch(void* const* d_in, const int* in_sizes, int n_in,
                              void* d_out, int out_size) {
    const float* x     = (const float*)d_in[0];
    const float* W1    = (const float*)d_in[1];
    const float* gamma = (const float*)d_in[2];
    const float* beta  = (const float*)d_in[3];
    const float* W4    = (const float*)d_in[4];
    float* out = (float*)d_out;

    zero_sums_kernel<<<1, HID>>>();
    packw_kernel<<<(HID * 128) / 8, 256>>>(W1);   // 6144 blocks

    cudaFuncSetAttribute(gemm_pop_kernel,
                         cudaFuncAttributeMaxDynamicSharedMemorySize, SMEMSZ);
    gemm_pop_kernel<<<BATCH / CTA_M, NTHR, SMEMSZ>>>(x);   // 512 CTAs, 1 wave

    stats_kernel<<<dim3(HID / 32, BATCH / 1024), 256>>>();
    finalize_kernel<<<1, HID>>>(gamma, beta);
    out_kernel<<<(BATCH * 32) / 256, 256>>>(W4, out);
}

// round 13
// speedup vs baseline: 1.4515x; 1.4246x over previous
#include <cuda_runtime.h>
#include <stdint.h>

#define BATCH 8192
#define IN_F  16384
#define HID   384
#define NOUT  10
#define KW    (IN_F / 32)      // 512 k-words total
#define KWC   8                // k-words per chunk
#define NCH   (KW / KWC)       // 64 chunks
#define CTA_M 8
#define NTHR  128

#define B_CH_W  (KWC * HID)    // 3072 words = 12288 B
#define A_CH_W  (KWC * CTA_M)  // 64 words = 256 B
#define B_BYTES (B_CH_W * 4)
#define A_BYTES (A_CH_W * 4)
#define SMEMSZ  (2 * (B_BYTES + A_BYTES))   // 25088 B

// ---------------- scratch globals ------------------------------------------
__device__ uint32_t  g_wbt[(size_t)KW * HID];   // W1 sign bits, [kword][hid]
__device__ short     g_h[(size_t)BATCH * HID];
__device__ long long g_sum[HID];
__device__ long long g_sumsq[HID];
__device__ float     g_A[HID];
__device__ float     g_B[HID];

// ---------------- PTX helpers ----------------------------------------------
__device__ __forceinline__ uint32_t smem_u32(const void* p) {
    uint32_t a;
    asm("{ .reg .u64 t; cvta.to.shared.u64 t, %1; cvt.u32.u64 %0, t; }"
        : "=r"(a) : "l"(p));
    return a;
}
#define CP16(s, g) \
    asm volatile("{ .reg .u64 gp; cvta.to.global.u64 gp, %1; " \
                 "cp.async.cg.shared.global [%0], [gp], 16; }" \
                 :: "r"(s), "l"(g) : "memory")
#define CPCOMMIT() asm volatile("cp.async.commit_group;" ::: "memory")
#define CPWAIT0()  asm volatile("cp.async.wait_group 0;" ::: "memory")
#define LDS4(r, a) \
    asm volatile("ld.shared.v4.b32 {%0,%1,%2,%3}, [%4];" \
                 : "=r"((r)[0]), "=r"((r)[1]), "=r"((r)[2]), "=r"((r)[3]) : "r"(a))
#define LDS2(r0, r1, a) \
    asm volatile("ld.shared.v2.b32 {%0,%1}, [%2];" \
                 : "=r"(r0), "=r"(r1) : "r"(a))

// ---------------- zero BN accumulators -------------------------------------
__global__ void zero_sums_kernel() {
    int j = threadIdx.x;
    if (j < HID) { g_sum[j] = 0; g_sumsq[j] = 0; }
}

// ---------------- W1 -> sign bits, transposed [kword][hid] ------------------
// kword (q*4+j), bit l  <->  W1[r, q*128 + 4*l + j]   (same perm used for x)
__global__ __launch_bounds__(256) void packw_kernel(const float* __restrict__ W1) {
    int gw   = (blockIdx.x * 256 + threadIdx.x) >> 5;
    int lane = threadIdx.x & 31;
    int r = gw >> 7;          // 0..383
    int q = gw & 127;         // 0..127
    float4 f = *reinterpret_cast<const float4*>(W1 + (size_t)r * IN_F + q * 128 + lane * 4);
    unsigned b0 = __ballot_sync(0xffffffffu, f.x < 0.f);
    unsigned b1 = __ballot_sync(0xffffffffu, f.y < 0.f);
    unsigned b2 = __ballot_sync(0xffffffffu, f.z < 0.f);
    unsigned b3 = __ballot_sync(0xffffffffu, f.w < 0.f);
    if (lane == 0) {
        g_wbt[(size_t)(q * 4 + 0) * HID + r] = b0;
        g_wbt[(size_t)(q * 4 + 1) * HID + r] = b1;
        g_wbt[(size_t)(q * 4 + 2) * HID + r] = b2;
        g_wbt[(size_t)(q * 4 + 3) * HID + r] = b3;
    }
}

// ---------------- CSA popcount GEMM, fused sign(x), low-reg -----------------
// 1024 CTAs (M=8, N=384, full K), 128 thr. Warp w: rows 2w, 2w+1.
// Lane n: cols 12n..12n+11. CSA state = 2x12 ones + 2x12 acc = 48 regs.
__global__ __launch_bounds__(NTHR, 4) void gemm_pop_kernel(const float* __restrict__ x) {
    extern __shared__ uint32_t smem[];
    const uint32_t sb  = smem_u32(smem);
    const int tid  = threadIdx.x;
    const int wid  = tid >> 5;
    const int lane = tid & 31;
    const int m0   = blockIdx.x * CTA_M;

    uint32_t ones[2][12];
    int      acc [2][12];
#pragma unroll
    for (int i = 0; i < 2; i++)
#pragma unroll
        for (int j = 0; j < 12; j++) { ones[i][j] = 0u; acc[i][j] = 0; }

    // B chunk: 12KB cp.async copy (6 x 16B per thread)
    auto loadB = [&](int c, int buf) {
        const char* src = (const char*)g_wbt + (size_t)c * B_BYTES;
        uint32_t dst = sb + buf * B_BYTES;
#pragma unroll
        for (int i = 0; i < 6; i++) {
            int u = tid + NTHR * i;
            CP16(dst + u * 16, src + (size_t)u * 16);
        }
    };
    // A chunk: read x fp32, ballot-binarize, store [kw][row] bit-words.
    // 16 tasks (8 rows x 2 col-groups of 128 floats), 4 per warp.
    auto convA = [&](int c, int buf) {
        uint32_t* As = smem + 2 * B_CH_W + buf * A_CH_W;
#pragma unroll
        for (int t = 0; t < 4; t++) {
            int G = wid * 4 + t;
            int row = G >> 1, gcol = G & 1;
            float4 f = *reinterpret_cast<const float4*>(
                x + (size_t)(m0 + row) * IN_F + c * (KWC * 32) + gcol * 128 + lane * 4);
            unsigned b0 = __ballot_sync(0xffffffffu, f.x < 0.f);
            unsigned b1 = __ballot_sync(0xffffffffu, f.y < 0.f);
            unsigned b2 = __ballot_sync(0xffffffffu, f.z < 0.f);
            unsigned b3 = __ballot_sync(0xffffffffu, f.w < 0.f);
            if (lane == 0) {
                As[(gcol * 4 + 0) * CTA_M + row] = b0;
                As[(gcol * 4 + 1) * CTA_M + row] = b1;
                As[(gcol * 4 + 2) * CTA_M + row] = b2;
                As[(gcol * 4 + 3) * CTA_M + row] = b3;
            }
        }
    };

    loadB(0, 0); CPCOMMIT();
    convA(0, 0);
    CPWAIT0(); __syncthreads();

    for (int c = 0; c < NCH; c++) {
        const int buf = c & 1;
        if (c + 1 < NCH) { loadB(c + 1, buf ^ 1); CPCOMMIT(); convA(c + 1, buf ^ 1); }

        const uint32_t bB = sb + buf * B_BYTES;
        const uint32_t bA = sb + 2 * B_BYTES + buf * A_BYTES;
#pragma unroll
        for (int kp = 0; kp < KWC / 2; kp++) {
            uint32_t a0[2], a1[2];
            LDS2(a0[0], a0[1], bA + (2 * kp)     * (CTA_M * 4) + wid * 8);
            LDS2(a1[0], a1[1], bA + (2 * kp + 1) * (CTA_M * 4) + wid * 8);
#pragma unroll
            for (int g = 0; g < 3; g++) {     // col groups of 4 (small live set)
                uint32_t b0[4], b1[4];
                LDS4(b0, bB + (2 * kp)     * (HID * 4) + lane * 48 + g * 16);
                LDS4(b1, bB + (2 * kp + 1) * (HID * 4) + lane * 48 + g * 16);
#pragma unroll
                for (int i = 0; i < 2; i++)
#pragma unroll
                    for (int jj = 0; jj < 4; jj++) {
                        const int j = g * 4 + jj;
                        uint32_t u = a0[i] ^ b0[jj];
                        uint32_t v = a1[i] ^ b1[jj];
                        uint32_t o = ones[i][j];
                        uint32_t cy = (o & u) | (o & v) | (u & v);  // LOP3 0xE8
                        ones[i][j] = o ^ u ^ v;                     // LOP3 0x96
                        acc[i][j] += __popc(cy);
                    }
            }
        }
        if (c + 1 < NCH) CPWAIT0();
        __syncthreads();
    }

    // mismatch = 2*acc + popc(ones);  h = IN_F - 2*mismatch
#pragma unroll
    for (int i = 0; i < 2; i++) {
        const int row = m0 + wid * 2 + i;
        short2* dst = reinterpret_cast<short2*>(g_h + (size_t)row * HID + lane * 12);
#pragma unroll
        for (int jp = 0; jp < 6; jp++) {
            int t0 = 2 * acc[i][2 * jp]     + __popc(ones[i][2 * jp]);
            int t1 = 2 * acc[i][2 * jp + 1] + __popc(ones[i][2 * jp + 1]);
            dst[jp] = make_short2((short)(IN_F - 2 * t0), (short)(IN_F - 2 * t1));
        }
    }
}

// ---------------- BN batch statistics (exact integer sums) -----------------
__global__ void stats_kernel() {
    const int cg = blockIdx.x, rc = blockIdx.y;
    const int c = threadIdx.x & 31, t = threadIdx.x >> 5;
    const int col = cg * 32 + c;
    int s = 0;
    long long s2 = 0;
    const int rbase = rc * 1024;
    for (int r = rbase + t; r < rbase + 1024; r += 8) {
        int v = g_h[(size_t)r * HID + col];
        s += v;
        s2 += (long long)v * v;
    }
    __shared__ int       ss [8][32];
    __shared__ long long ss2[8][32];
    ss[t][c] = s; ss2[t][c] = s2;
    __syncthreads();
    if (t == 0) {
        long long S = 0, S2 = 0;
#pragma unroll
        for (int u = 0; u < 8; u++) { S += ss[u][c]; S2 += ss2[u][c]; }
        atomicAdd((unsigned long long*)&g_sum[col],   (unsigned long long)S);
        atomicAdd((unsigned long long*)&g_sumsq[col], (unsigned long long)S2);
    }
}

// ---------------- fold BN into affine --------------------------------------
__global__ void finalize_kernel(const float* __restrict__ gamma,
                                const float* __restrict__ beta) {
    int j = threadIdx.x;
    if (j >= HID) return;
    double mean = (double)g_sum[j]   / (double)BATCH;
    double var  = (double)g_sumsq[j] / (double)BATCH - mean * mean;
    float a = gamma[j] * (float)(1.0 / sqrt(var + 1e-5));
    g_A[j] = a;
    g_B[j] = beta[j] - (float)mean * a;
}

// ---------------- output layer ---------------------------------------------
__global__ __launch_bounds__(256) void out_kernel(const float* __restrict__ W4,
                                                  float* __restrict__ out) {
    int gt = blockIdx.x * blockDim.x + threadIdx.x;
    int row = gt >> 5, lane = gt & 31;
    if (row >= BATCH) return;
    float acc[NOUT];
#pragma unroll
    for (int o = 0; o < NOUT; o++) acc[o] = 0.f;
    for (int j = lane; j < HID; j += 32) {
        int hv = g_h[(size_t)row * HID + j];
        float v = (float)hv * g_A[j] + g_B[j];
        float s = (v > 0.f) ? 1.f : ((v < 0.f) ? -1.f : 0.f);
#pragma unroll
        for (int o = 0; o < NOUT; o++) {
            float w = __ldg(&W4[o * HID + j]);
            float ws = (w > 0.f) ? 1.f : ((w < 0.f) ? -1.f : 0.f);
            acc[o] = fmaf(s, ws, acc[o]);
        }
    }
#pragma unroll
    for (int o = 0; o < NOUT; o++)
#pragma unroll
        for (int off = 16; off; off >>= 1)
            acc[o] += __shfl_down_sync(0xffffffffu, acc[o], off);
    if (lane == 0) {
#pragma unroll
        for (int o = 0; o < NOUT; o++) out[(size_t)row * NOUT + o] = acc[o];
    }
}

// ---------------- launch ----------------------------------------------------
extern "C" void kernel_launch(void* const* d_in, const int* in_sizes, int n_in,
                              void* d_out, int out_size) {
    const float* x     = (const float*)d_in[0];
    const float* W1    = (const float*)d_in[1];
    const float* gamma = (const float*)d_in[2];
    const float* beta  = (const float*)d_in[3];
    const float* W4    = (const float*)d_in[4];
    float* out = (float*)d_out;

    zero_sums_kernel<<<1, HID>>>();
    packw_kernel<<<(HID * 128) / 8, 256>>>(W1);   // 6144 blocks

    cudaFuncSetAttribute(gemm_pop_kernel,
                         cudaFuncAttributeMaxDynamicSharedMemorySize, SMEMSZ);
    gemm_pop_kernel<<<BATCH / CTA_M, NTHR, SMEMSZ>>>(x);   // 1024 CTAs

    stats_kernel<<<dim3(HID / 32, BATCH / 1024), 256>>>();
    finalize_kernel<<<1, HID>>>(gamma, beta);
    out_kernel<<<(BATCH * 32) / 256, 256>>>(W4, out);
}

// round 14
// speedup vs baseline: 1.8245x; 1.2570x over previous
#include <cuda_runtime.h>
#include <stdint.h>

#define BATCH 8192
#define IN_F  16384
#define HID   384
#define NOUT  10
#define KW    (IN_F / 32)      // 512 k-words total
#define KWC   8                // k-words per chunk
#define NCH   (KW / KWC)       // 64 chunks
#define CTA_M 8
#define NTHR  128

#define B_CH_W  (KWC * HID)    // 3072 words = 12288 B
#define A_CH_W  (KWC * CTA_M)  // 64 words = 256 B
#define B_BYTES (B_CH_W * 4)
#define A_BYTES (A_CH_W * 4)
#define SMEMSZ  (2 * (B_BYTES + A_BYTES))   // 25088 B

// ---------------- scratch globals ------------------------------------------
__device__ uint32_t  g_wbt[(size_t)KW * HID];   // W1 sign bits, [kword][hid]
__device__ short     g_h[(size_t)BATCH * HID];
__device__ long long g_sum[HID];
__device__ long long g_sumsq[HID];
__device__ float     g_A[HID];
__device__ float     g_B[HID];

// ---------------- PTX helpers ----------------------------------------------
__device__ __forceinline__ uint32_t smem_u32(const void* p) {
    uint32_t a;
    asm("{ .reg .u64 t; cvta.to.shared.u64 t, %1; cvt.u32.u64 %0, t; }"
        : "=r"(a) : "l"(p));
    return a;
}
#define CP16(s, g) \
    asm volatile("{ .reg .u64 gp; cvta.to.global.u64 gp, %1; " \
                 "cp.async.cg.shared.global [%0], [gp], 16; }" \
                 :: "r"(s), "l"(g) : "memory")
#define CPCOMMIT() asm volatile("cp.async.commit_group;" ::: "memory")
#define CPWAIT0()  asm volatile("cp.async.wait_group 0;" ::: "memory")
#define LDS4(r, a) \
    asm volatile("ld.shared.v4.b32 {%0,%1,%2,%3}, [%4];" \
                 : "=r"((r)[0]), "=r"((r)[1]), "=r"((r)[2]), "=r"((r)[3]) : "r"(a))
#define LDS2(r0, r1, a) \
    asm volatile("ld.shared.v2.b32 {%0,%1}, [%2];" \
                 : "=r"(r0), "=r"(r1) : "r"(a))

// Explicit single-instruction LOP3s for the CSA compressor.
__device__ __forceinline__ uint32_t lop3_maj(uint32_t a, uint32_t b, uint32_t c) {
    uint32_t r;
    asm("lop3.b32 %0, %1, %2, %3, 0xE8;" : "=r"(r) : "r"(a), "r"(b), "r"(c));
    return r;   // (a&b)|(a&c)|(b&c)
}
__device__ __forceinline__ uint32_t lop3_xor3(uint32_t a, uint32_t b, uint32_t c) {
    uint32_t r;
    asm("lop3.b32 %0, %1, %2, %3, 0x96;" : "=r"(r) : "r"(a), "r"(b), "r"(c));
    return r;   // a^b^c
}

// ---------------- zero BN accumulators -------------------------------------
__global__ void zero_sums_kernel() {
    int j = threadIdx.x;
    if (j < HID) { g_sum[j] = 0; g_sumsq[j] = 0; }
}

// ---------------- W1 -> sign bits, transposed [kword][hid] ------------------
// kword (q*4+j), bit l  <->  W1[r, q*128 + 4*l + j]   (same perm used for x)
__global__ __launch_bounds__(256) void packw_kernel(const float* __restrict__ W1) {
    int gw   = (blockIdx.x * 256 + threadIdx.x) >> 5;
    int lane = threadIdx.x & 31;
    int r = gw >> 7;          // 0..383
    int q = gw & 127;         // 0..127
    float4 f = *reinterpret_cast<const float4*>(W1 + (size_t)r * IN_F + q * 128 + lane * 4);
    unsigned b0 = __ballot_sync(0xffffffffu, f.x < 0.f);
    unsigned b1 = __ballot_sync(0xffffffffu, f.y < 0.f);
    unsigned b2 = __ballot_sync(0xffffffffu, f.z < 0.f);
    unsigned b3 = __ballot_sync(0xffffffffu, f.w < 0.f);
    if (lane == 0) {
        g_wbt[(size_t)(q * 4 + 0) * HID + r] = b0;
        g_wbt[(size_t)(q * 4 + 1) * HID + r] = b1;
        g_wbt[(size_t)(q * 4 + 2) * HID + r] = b2;
        g_wbt[(size_t)(q * 4 + 3) * HID + r] = b3;
    }
}

// ---------------- CSA popcount GEMM, fused sign(x), low-reg -----------------
// 1024 CTAs (M=8, N=384, full K), 128 thr. Warp w: rows 2w, 2w+1.
// Lane n: cols 12n..12n+11. CSA state = 2x12 ones + 2x12 acc = 48 regs.
// Compressor forced to single LOP3s (0xE8 maj, 0x96 xor3).
__global__ __launch_bounds__(NTHR, 4) void gemm_pop_kernel(const float* __restrict__ x) {
    extern __shared__ uint32_t smem[];
    const uint32_t sb  = smem_u32(smem);
    const int tid  = threadIdx.x;
    const int wid  = tid >> 5;
    const int lane = tid & 31;
    const int m0   = blockIdx.x * CTA_M;

    uint32_t ones[2][12];
    int      acc [2][12];
#pragma unroll
    for (int i = 0; i < 2; i++)
#pragma unroll
        for (int j = 0; j < 12; j++) { ones[i][j] = 0u; acc[i][j] = 0; }

    // B chunk: 12KB cp.async copy (6 x 16B per thread)
    auto loadB = [&](int c, int buf) {
        const char* src = (const char*)g_wbt + (size_t)c * B_BYTES;
        uint32_t dst = sb + buf * B_BYTES;
#pragma unroll
        for (int i = 0; i < 6; i++) {
            int u = tid + NTHR * i;
            CP16(dst + u * 16, src + (size_t)u * 16);
        }
    };
    // A chunk: read x fp32, ballot-binarize, store [kw][row] bit-words.
    // 16 tasks (8 rows x 2 col-groups of 128 floats), 4 per warp.
    auto convA = [&](int c, int buf) {
        uint32_t* As = smem + 2 * B_CH_W + buf * A_CH_W;
#pragma unroll
        for (int t = 0; t < 4; t++) {
            int G = wid * 4 + t;
            int row = G >> 1, gcol = G & 1;
            float4 f = *reinterpret_cast<const float4*>(
                x + (size_t)(m0 + row) * IN_F + c * (KWC * 32) + gcol * 128 + lane * 4);
            unsigned b0 = __ballot_sync(0xffffffffu, f.x < 0.f);
            unsigned b1 = __ballot_sync(0xffffffffu, f.y < 0.f);
            unsigned b2 = __ballot_sync(0xffffffffu, f.z < 0.f);
            unsigned b3 = __ballot_sync(0xffffffffu, f.w < 0.f);
            if (lane == 0) {
                As[(gcol * 4 + 0) * CTA_M + row] = b0;
                As[(gcol * 4 + 1) * CTA_M + row] = b1;
                As[(gcol * 4 + 2) * CTA_M + row] = b2;
                As[(gcol * 4 + 3) * CTA_M + row] = b3;
            }
        }
    };

    loadB(0, 0); CPCOMMIT();
    convA(0, 0);
    CPWAIT0(); __syncthreads();

    for (int c = 0; c < NCH; c++) {
        const int buf = c & 1;
        if (c + 1 < NCH) { loadB(c + 1, buf ^ 1); CPCOMMIT(); convA(c + 1, buf ^ 1); }

        const uint32_t bB = sb + buf * B_BYTES;
        const uint32_t bA = sb + 2 * B_BYTES + buf * A_BYTES;
#pragma unroll
        for (int kp = 0; kp < KWC / 2; kp++) {
            uint32_t a0[2], a1[2];
            LDS2(a0[0], a0[1], bA + (2 * kp)     * (CTA_M * 4) + wid * 8);
            LDS2(a1[0], a1[1], bA + (2 * kp + 1) * (CTA_M * 4) + wid * 8);
#pragma unroll
            for (int g = 0; g < 3; g++) {     // col groups of 4 (small live set)
                uint32_t b0[4], b1[4];
                LDS4(b0, bB + (2 * kp)     * (HID * 4) + lane * 48 + g * 16);
                LDS4(b1, bB + (2 * kp + 1) * (HID * 4) + lane * 48 + g * 16);
#pragma unroll
                for (int i = 0; i < 2; i++)
#pragma unroll
                    for (int jj = 0; jj < 4; jj++) {
                        const int j = g * 4 + jj;
                        uint32_t u = a0[i] ^ b0[jj];
                        uint32_t v = a1[i] ^ b1[jj];
                        uint32_t o = ones[i][j];
                        uint32_t cy = lop3_maj(o, u, v);   // 1 LOP3
                        ones[i][j] = lop3_xor3(o, u, v);   // 1 LOP3
                        acc[i][j] += __popc(cy);
                    }
            }
        }
        if (c + 1 < NCH) CPWAIT0();
        __syncthreads();
    }

    // mismatch = 2*acc + popc(ones);  h = IN_F - 2*mismatch
#pragma unroll
    for (int i = 0; i < 2; i++) {
        const int row = m0 + wid * 2 + i;
        short2* dst = reinterpret_cast<short2*>(g_h + (size_t)row * HID + lane * 12);
#pragma unroll
        for (int jp = 0; jp < 6; jp++) {
            int t0 = 2 * acc[i][2 * jp]     + __popc(ones[i][2 * jp]);
            int t1 = 2 * acc[i][2 * jp + 1] + __popc(ones[i][2 * jp + 1]);
            dst[jp] = make_short2((short)(IN_F - 2 * t0), (short)(IN_F - 2 * t1));
        }
    }
}

// ---------------- BN batch statistics (exact integer sums) -----------------
__global__ void stats_kernel() {
    const int cg = blockIdx.x, rc = blockIdx.y;
    const int c = threadIdx.x & 31, t = threadIdx.x >> 5;
    const int col = cg * 32 + c;
    int s = 0;
    long long s2 = 0;
    const int rbase = rc * 1024;
    for (int r = rbase + t; r < rbase + 1024; r += 8) {
        int v = g_h[(size_t)r * HID + col];
        s += v;
        s2 += (long long)v * v;
    }
    __shared__ int       ss [8][32];
    __shared__ long long ss2[8][32];
    ss[t][c] = s; ss2[t][c] = s2;
    __syncthreads();
    if (t == 0) {
        long long S = 0, S2 = 0;
#pragma unroll
        for (int u = 0; u < 8; u++) { S += ss[u][c]; S2 += ss2[u][c]; }
        atomicAdd((unsigned long long*)&g_sum[col],   (unsigned long long)S);
        atomicAdd((unsigned long long*)&g_sumsq[col], (unsigned long long)S2);
    }
}

// ---------------- fold BN into affine --------------------------------------
__global__ void finalize_kernel(const float* __restrict__ gamma,
                                const float* __restrict__ beta) {
    int j = threadIdx.x;
    if (j >= HID) return;
    double mean = (double)g_sum[j]   / (double)BATCH;
    double var  = (double)g_sumsq[j] / (double)BATCH - mean * mean;
    float a = gamma[j] * (float)(1.0 / sqrt(var + 1e-5));
    g_A[j] = a;
    g_B[j] = beta[j] - (float)mean * a;
}

// ---------------- output layer ---------------------------------------------
__global__ __launch_bounds__(256) void out_kernel(const float* __restrict__ W4,
                                                  float* __restrict__ out) {
    int gt = blockIdx.x * blockDim.x + threadIdx.x;
    int row = gt >> 5, lane = gt & 31;
    if (row >= BATCH) return;
    float acc[NOUT];
#pragma unroll
    for (int o = 0; o < NOUT; o++) acc[o] = 0.f;
    for (int j = lane; j < HID; j += 32) {
        int hv = g_h[(size_t)row * HID + j];
        float v = (float)hv * g_A[j] + g_B[j];
        float s = (v > 0.f) ? 1.f : ((v < 0.f) ? -1.f : 0.f);
#pragma unroll
        for (int o = 0; o < NOUT; o++) {
            float w = __ldg(&W4[o * HID + j]);
            float ws = (w > 0.f) ? 1.f : ((w < 0.f) ? -1.f : 0.f);
            acc[o] = fmaf(s, ws, acc[o]);
        }
    }
#pragma unroll
    for (int o = 0; o < NOUT; o++)
#pragma unroll
        for (int off = 16; off; off >>= 1)
            acc[o] += __shfl_down_sync(0xffffffffu, acc[o], off);
    if (lane == 0) {
#pragma unroll
        for (int o = 0; o < NOUT; o++) out[(size_t)row * NOUT + o] = acc[o];
    }
}

// ---------------- launch ----------------------------------------------------
extern "C" void kernel_launch(void* const* d_in, const int* in_sizes, int n_in,
                              void* d_out, int out_size) {
    const float* x     = (const float*)d_in[0];
    const float* W1    = (const float*)d_in[1];
    const float* gamma = (const float*)d_in[2];
    const float* beta  = (const float*)d_in[3];
    const float* W4    = (const float*)d_in[4];
    float* out = (float*)d_out;

    zero_sums_kernel<<<1, HID>>>();
    packw_kernel<<<(HID * 128) / 8, 256>>>(W1);   // 6144 blocks

    cudaFuncSetAttribute(gemm_pop_kernel,
                         cudaFuncAttributeMaxDynamicSharedMemorySize, SMEMSZ);
    gemm_pop_kernel<<<BATCH / CTA_M, NTHR, SMEMSZ>>>(x);   // 1024 CTAs

    stats_kernel<<<dim3(HID / 32, BATCH / 1024), 256>>>();
    finalize_kernel<<<1, HID>>>(gamma, beta);
    out_kernel<<<(BATCH * 32) / 256, 256>>>(W4, out);
}

// round 15
// speedup vs baseline: 1.9662x; 1.0777x over previous
#include <cuda_runtime.h>
#include <stdint.h>

#define BATCH 8192
#define IN_F  16384
#define HID   384
#define NOUT  10
#define KW    (IN_F / 32)      // 512 k-words total
#define KWC   8                // k-words per chunk
#define NCH   (KW / KWC)       // 64 chunks
#define CTA_M 8
#define NTHR  128

#define B_CH_W  (KWC * HID)    // 3072 words = 12288 B
#define A_CH_W  (KWC * CTA_M)  // 64 words = 256 B
#define B_BYTES (B_CH_W * 4)
#define A_BYTES (A_CH_W * 4)
#define SMEMSZ  (2 * (B_BYTES + A_BYTES))   // 25088 B

// ---------------- scratch globals ------------------------------------------
__device__ uint32_t  g_wbt[(size_t)KW * HID];   // W1 sign bits, [kword][hid]
__device__ short     g_h[(size_t)BATCH * HID];
__device__ long long g_sum[HID];
__device__ long long g_sumsq[HID];
__device__ float     g_A[HID];
__device__ float     g_B[HID];
__device__ float     g_ws[NOUT * HID];          // sign(W4)

// ---------------- PTX helpers ----------------------------------------------
__device__ __forceinline__ uint32_t smem_u32(const void* p) {
    uint32_t a;
    asm("{ .reg .u64 t; cvta.to.shared.u64 t, %1; cvt.u32.u64 %0, t; }"
        : "=r"(a) : "l"(p));
    return a;
}
#define CP16(s, g) \
    asm volatile("{ .reg .u64 gp; cvta.to.global.u64 gp, %1; " \
                 "cp.async.cg.shared.global [%0], [gp], 16; }" \
                 :: "r"(s), "l"(g) : "memory")
#define CPCOMMIT() asm volatile("cp.async.commit_group;" ::: "memory")
#define CPWAIT0()  asm volatile("cp.async.wait_group 0;" ::: "memory")
#define LDS4(r, a) \
    asm volatile("ld.shared.v4.b32 {%0,%1,%2,%3}, [%4];" \
                 : "=r"((r)[0]), "=r"((r)[1]), "=r"((r)[2]), "=r"((r)[3]) : "r"(a))
#define LDS2(r0, r1, a) \
    asm volatile("ld.shared.v2.b32 {%0,%1}, [%2];" \
                 : "=r"(r0), "=r"(r1) : "r"(a))

// Explicit single-instruction LOP3s for the CSA compressor.
__device__ __forceinline__ uint32_t lop3_maj(uint32_t a, uint32_t b, uint32_t c) {
    uint32_t r;
    asm("lop3.b32 %0, %1, %2, %3, 0xE8;" : "=r"(r) : "r"(a), "r"(b), "r"(c));
    return r;   // (a&b)|(a&c)|(b&c)
}
__device__ __forceinline__ uint32_t lop3_xor3(uint32_t a, uint32_t b, uint32_t c) {
    uint32_t r;
    asm("lop3.b32 %0, %1, %2, %3, 0x96;" : "=r"(r) : "r"(a), "r"(b), "r"(c));
    return r;   // a^b^c
}

// ---------------- W1 -> sign bits (transposed) + zero BN accumulators -------
// kword (q*4+j), bit l  <->  W1[r, q*128 + 4*l + j]   (same perm used for x)
__global__ __launch_bounds__(256) void packw_kernel(const float* __restrict__ W1) {
    int g = blockIdx.x * 256 + threadIdx.x;
    if (g < HID) { g_sum[g] = 0; g_sumsq[g] = 0; }   // blocks 0-1 zero BN sums
    int gw   = g >> 5;
    int lane = threadIdx.x & 31;
    int r = gw >> 7;          // 0..383
    int q = gw & 127;         // 0..127
    float4 f = *reinterpret_cast<const float4*>(W1 + (size_t)r * IN_F + q * 128 + lane * 4);
    unsigned b0 = __ballot_sync(0xffffffffu, f.x < 0.f);
    unsigned b1 = __ballot_sync(0xffffffffu, f.y < 0.f);
    unsigned b2 = __ballot_sync(0xffffffffu, f.z < 0.f);
    unsigned b3 = __ballot_sync(0xffffffffu, f.w < 0.f);
    if (lane == 0) {
        g_wbt[(size_t)(q * 4 + 0) * HID + r] = b0;
        g_wbt[(size_t)(q * 4 + 1) * HID + r] = b1;
        g_wbt[(size_t)(q * 4 + 2) * HID + r] = b2;
        g_wbt[(size_t)(q * 4 + 3) * HID + r] = b3;
    }
}

// ---------------- CSA popcount GEMM, fused sign(x) + fused BN stats ---------
// 1024 CTAs (M=8, N=384, full K), 128 thr. Warp w: rows 2w, 2w+1.
// Lane n: cols 12n..12n+11. CSA state = 2x12 ones + 2x12 acc = 48 regs.
__global__ __launch_bounds__(NTHR, 4) void gemm_pop_kernel(const float* __restrict__ x) {
    extern __shared__ uint32_t smem[];
    const uint32_t sb  = smem_u32(smem);
    const int tid  = threadIdx.x;
    const int wid  = tid >> 5;
    const int lane = tid & 31;
    const int m0   = blockIdx.x * CTA_M;

    uint32_t ones[2][12];
    int      acc [2][12];
#pragma unroll
    for (int i = 0; i < 2; i++)
#pragma unroll
        for (int j = 0; j < 12; j++) { ones[i][j] = 0u; acc[i][j] = 0; }

    // B chunk: 12KB cp.async copy (6 x 16B per thread)
    auto loadB = [&](int c, int buf) {
        const char* src = (const char*)g_wbt + (size_t)c * B_BYTES;
        uint32_t dst = sb + buf * B_BYTES;
#pragma unroll
        for (int i = 0; i < 6; i++) {
            int u = tid + NTHR * i;
            CP16(dst + u * 16, src + (size_t)u * 16);
        }
    };
    // A chunk: read x fp32, ballot-binarize, store [kw][row] bit-words.
    auto convA = [&](int c, int buf) {
        uint32_t* As = smem + 2 * B_CH_W + buf * A_CH_W;
#pragma unroll
        for (int t = 0; t < 4; t++) {
            int G = wid * 4 + t;
            int row = G >> 1, gcol = G & 1;
            float4 f = *reinterpret_cast<const float4*>(
                x + (size_t)(m0 + row) * IN_F + c * (KWC * 32) + gcol * 128 + lane * 4);
            unsigned b0 = __ballot_sync(0xffffffffu, f.x < 0.f);
            unsigned b1 = __ballot_sync(0xffffffffu, f.y < 0.f);
            unsigned b2 = __ballot_sync(0xffffffffu, f.z < 0.f);
            unsigned b3 = __ballot_sync(0xffffffffu, f.w < 0.f);
            if (lane == 0) {
                As[(gcol * 4 + 0) * CTA_M + row] = b0;
                As[(gcol * 4 + 1) * CTA_M + row] = b1;
                As[(gcol * 4 + 2) * CTA_M + row] = b2;
                As[(gcol * 4 + 3) * CTA_M + row] = b3;
            }
        }
    };

    loadB(0, 0); CPCOMMIT();
    convA(0, 0);
    CPWAIT0(); __syncthreads();

    for (int c = 0; c < NCH; c++) {
        const int buf = c & 1;
        if (c + 1 < NCH) { loadB(c + 1, buf ^ 1); CPCOMMIT(); convA(c + 1, buf ^ 1); }

        const uint32_t bB = sb + buf * B_BYTES;
        const uint32_t bA = sb + 2 * B_BYTES + buf * A_BYTES;
#pragma unroll
        for (int kp = 0; kp < KWC / 2; kp++) {
            uint32_t a0[2], a1[2];
            LDS2(a0[0], a0[1], bA + (2 * kp)     * (CTA_M * 4) + wid * 8);
            LDS2(a1[0], a1[1], bA + (2 * kp + 1) * (CTA_M * 4) + wid * 8);
#pragma unroll
            for (int g = 0; g < 3; g++) {
                uint32_t b0[4], b1[4];
                LDS4(b0, bB + (2 * kp)     * (HID * 4) + lane * 48 + g * 16);
                LDS4(b1, bB + (2 * kp + 1) * (HID * 4) + lane * 48 + g * 16);
#pragma unroll
                for (int i = 0; i < 2; i++)
#pragma unroll
                    for (int jj = 0; jj < 4; jj++) {
                        const int j = g * 4 + jj;
                        uint32_t u = a0[i] ^ b0[jj];
                        uint32_t v = a1[i] ^ b1[jj];
                        uint32_t o = ones[i][j];
                        uint32_t cy = lop3_maj(o, u, v);   // 1 LOP3
                        ones[i][j] = lop3_xor3(o, u, v);   // 1 LOP3
                        acc[i][j] += __popc(cy);
                    }
            }
        }
        if (c + 1 < NCH) CPWAIT0();
        __syncthreads();
    }

    // ---- epilogue: h values + fused BN partial sums -------------------------
    int hv[2][12];
#pragma unroll
    for (int i = 0; i < 2; i++) {
#pragma unroll
        for (int jp = 0; jp < 12; jp++) {
            int t = 2 * acc[i][jp] + __popc(ones[i][jp]);
            hv[i][jp] = IN_F - 2 * t;
        }
        const int row = m0 + wid * 2 + i;
        short2* dst = reinterpret_cast<short2*>(g_h + (size_t)row * HID + lane * 12);
#pragma unroll
        for (int jp = 0; jp < 6; jp++)
            dst[jp] = make_short2((short)hv[i][2 * jp], (short)hv[i][2 * jp + 1]);
    }

    // per-CTA column sums via smem (each slot written exactly once), then atomics
    int*      s_sm = (int*)smem;               // [4][HID]
    unsigned* q_sm = (unsigned*)smem + 4 * HID;// [4][HID]
#pragma unroll
    for (int jp = 0; jp < 12; jp++) {
        const int col = lane * 12 + jp;
        s_sm[wid * HID + col] = hv[0][jp] + hv[1][jp];
        q_sm[wid * HID + col] = (unsigned)(hv[0][jp] * hv[0][jp]) +
                                (unsigned)(hv[1][jp] * hv[1][jp]);
    }
    __syncthreads();
    for (int col = tid; col < HID; col += NTHR) {
        long long S = (long long)s_sm[col] + s_sm[HID + col] +
                      s_sm[2 * HID + col] + s_sm[3 * HID + col];
        unsigned long long Q = (unsigned long long)q_sm[col] + q_sm[HID + col] +
                               q_sm[2 * HID + col] + q_sm[3 * HID + col];
        atomicAdd((unsigned long long*)&g_sum[col], (unsigned long long)S);
        atomicAdd((unsigned long long*)&g_sumsq[col], Q);
    }
}

// ---------------- fold BN into affine + precompute sign(W4) -----------------
__global__ __launch_bounds__(256) void finalize_kernel(const float* __restrict__ gamma,
                                                       const float* __restrict__ beta,
                                                       const float* __restrict__ W4) {
    int j = blockIdx.x * 256 + threadIdx.x;
    if (j < HID) {
        double mean = (double)g_sum[j]   / (double)BATCH;
        double var  = (double)g_sumsq[j] / (double)BATCH - mean * mean;
        float a = gamma[j] * (float)(1.0 / sqrt(var + 1e-5));
        g_A[j] = a;
        g_B[j] = beta[j] - (float)mean * a;
    }
    if (j < NOUT * HID) {
        float w = W4[j];
        g_ws[j] = (w > 0.f) ? 1.f : ((w < 0.f) ? -1.f : 0.f);
    }
}

// ---------------- output layer ---------------------------------------------
__global__ __launch_bounds__(256) void out_kernel(float* __restrict__ out) {
    int gt = blockIdx.x * blockDim.x + threadIdx.x;
    int row = gt >> 5, lane = gt & 31;
    if (row >= BATCH) return;
    float acc[NOUT];
#pragma unroll
    for (int o = 0; o < NOUT; o++) acc[o] = 0.f;
    for (int j = lane; j < HID; j += 32) {
        int hv = g_h[(size_t)row * HID + j];
        float v = (float)hv * g_A[j] + g_B[j];
        float s = (v > 0.f) ? 1.f : ((v < 0.f) ? -1.f : 0.f);
#pragma unroll
        for (int o = 0; o < NOUT; o++)
            acc[o] = fmaf(s, __ldg(&g_ws[o * HID + j]), acc[o]);
    }
#pragma unroll
    for (int o = 0; o < NOUT; o++)
#pragma unroll
        for (int off = 16; off; off >>= 1)
            acc[o] += __shfl_down_sync(0xffffffffu, acc[o], off);
    if (lane == 0) {
#pragma unroll
        for (int o = 0; o < NOUT; o++) out[(size_t)row * NOUT + o] = acc[o];
    }
}

// ---------------- launch ----------------------------------------------------
extern "C" void kernel_launch(void* const* d_in, const int* in_sizes, int n_in,
                              void* d_out, int out_size) {
    const float* x     = (const float*)d_in[0];
    const float* W1    = (const float*)d_in[1];
    const float* gamma = (const float*)d_in[2];
    const float* beta  = (const float*)d_in[3];
    const float* W4    = (const float*)d_in[4];
    float* out = (float*)d_out;

    packw_kernel<<<(HID * 128) / 8, 256>>>(W1);   // 6144 blocks (+BN zeroing)

    cudaFuncSetAttribute(gemm_pop_kernel,
                         cudaFuncAttributeMaxDynamicSharedMemorySize, SMEMSZ);
    gemm_pop_kernel<<<BATCH / CTA_M, NTHR, SMEMSZ>>>(x);   // 1024 CTAs

    finalize_kernel<<<(NOUT * HID + 255) / 256, 256>>>(gamma, beta, W4);
    out_kernel<<<(BATCH * 32) / 256, 256>>>(out);
}